// round 3
// baseline (speedup 1.0000x reference)
#include <cuda_runtime.h>
#include <cstdint>

#define NX 128
#define NU 64
#define ND 192
#define TH 2048
#define GB 32      // backward grid blocks (co-resident, 32 <= 148 SMs)
#define NT 256
#define RPB 6      // Q rows per block: 192/32

// ---------------- static device scratch (no allocations allowed) ----------------
__device__ __align__(16) float g_Ft[ND * NX];          // F^T, 192x128
__device__ __align__(16) float g_Vb[2][NX * NX];
__device__ __align__(16) float g_vb[2][NX];
__device__ __align__(16) float g_Q[ND * ND];
__device__ __align__(16) float g_q[ND];
__device__ __align__(16) float g_inv[NU * NU];
__device__ float g_Ks[(size_t)TH * NU * NX];           // 64 MB
__device__ float g_ks[TH * NU];
__device__ float g_Ms[(size_t)TH * NX * NX];           // 128 MB
__device__ float g_bs[TH * NX];
__device__ unsigned g_delta[TH];
__device__ unsigned g_vmax[TH];
__device__ int g_niters;
__device__ unsigned g_barcnt = 0;
__device__ unsigned g_bargen = 0;

// ---------------- grid barrier (generation-based, fenced) ----------------
__device__ __forceinline__ void gbar() {
    __syncthreads();
    if (threadIdx.x == 0) {
        __threadfence();
        volatile unsigned* vg = &g_bargen;
        unsigned gen = *vg;
        if (atomicAdd(&g_barcnt, 1u) == (unsigned)(GB - 1)) {
            g_barcnt = 0u;
            __threadfence();
            atomicAdd(&g_bargen, 1u);
        } else {
            while (*vg == gen) { __nanosleep(64); }
        }
        __threadfence();
    }
    __syncthreads();
}

// ---------------- setup ----------------
__global__ void __launch_bounds__(NT) k_setup(const float* __restrict__ F,
                                              const float* __restrict__ C,
                                              const float* __restrict__ c) {
    int idx = blockIdx.x * NT + threadIdx.x;
    if (idx < ND * NX) {
        int i = idx / NX, m = idx - i * NX;
        g_Ft[i * NX + m] = F[m * ND + i];
    }
    if (idx < NX * NX) {
        int i = idx >> 7, j = idx & 127;
        g_Vb[0][idx] = C[i * ND + j];
    }
    if (idx < NX) g_vb[0][idx] = c[idx];
    if (idx < TH) { g_delta[idx] = 0u; g_vmax[idx] = 0u; }
    if (idx == 0) g_niters = TH;
}

// ---------------- backward Riccati (persistent, 32 CTAs) ----------------
__global__ void __launch_bounds__(NT) k_backward(const float* __restrict__ F,
                                                 const float* __restrict__ f,
                                                 const float* __restrict__ C,
                                                 const float* __restrict__ c) {
    const int b = blockIdx.x, tid = threadIdx.x;

    __shared__ float ft2[2][NX];
    __shared__ float fv2[2][NX];
    __shared__ float qred[8];
    __shared__ float prA[64], prI[64], fsh[64];
    __shared__ float pivsh;
    __shared__ float rmax[8], rvmx[8];

    for (int it = 0; it < TH; ++it) {
        const int p = it & 1;
        const float* V  = g_Vb[p];
        const float* v  = g_vb[p];
        float* Vn = g_Vb[p ^ 1];
        float* vn = g_vb[p ^ 1];

        // ===== phase 1: this CTA's 6 rows of Q (and q) =====
        const int i0 = b * RPB;
        for (int pr = 0; pr < RPB; pr += 2) {
            const int ri = tid >> 7;     // which of the 2 rows
            const int m  = tid & 127;
            const int i  = i0 + pr + ri;
            ft2[ri][m] = g_Ft[i * NX + m];
            __syncthreads();
            // FV row: FV[i][m] = sum_k Ft[i][k] * V[k][m]
            float a0 = 0.f, a1 = 0.f, a2 = 0.f, a3 = 0.f;
            #pragma unroll 8
            for (int k = 0; k < NX; k += 4) {
                a0 += ft2[ri][k    ] * __ldcg(&V[(k    ) * NX + m]);
                a1 += ft2[ri][k + 1] * __ldcg(&V[(k + 1) * NX + m]);
                a2 += ft2[ri][k + 2] * __ldcg(&V[(k + 2) * NX + m]);
                a3 += ft2[ri][k + 3] * __ldcg(&V[(k + 3) * NX + m]);
            }
            float fv = (a0 + a1) + (a2 + a3);
            fv2[ri][m] = fv;
            // q partial: FV[i][m]*f[m] + Ft[i][m]*v[m]
            float pq = fv * f[m] + ft2[ri][m] * __ldcg(&v[m]);
            #pragma unroll
            for (int o = 16; o > 0; o >>= 1) pq += __shfl_down_sync(0xffffffffu, pq, o);
            if ((tid & 31) == 0) qred[tid >> 5] = pq;
            __syncthreads();
            if (tid < 2) {
                float s = qred[tid * 4] + qred[tid * 4 + 1] + qred[tid * 4 + 2] + qred[tid * 4 + 3];
                g_q[i0 + pr + tid] = c[i0 + pr + tid] + s;
            }
            // Q rows: Q[i][j] = C[i][j] + sum_m FV[i][m] * F[m][j]
            #pragma unroll
            for (int rr = 0; rr < 2; ++rr) {
                const int irow = i0 + pr + rr;
                if (tid < ND) {
                    float b0 = 0.f, b1 = 0.f, b2 = 0.f, b3 = 0.f;
                    #pragma unroll 8
                    for (int mm = 0; mm < NX; mm += 4) {
                        b0 += fv2[rr][mm    ] * F[(mm    ) * ND + tid];
                        b1 += fv2[rr][mm + 1] * F[(mm + 1) * ND + tid];
                        b2 += fv2[rr][mm + 2] * F[(mm + 2) * ND + tid];
                        b3 += fv2[rr][mm + 3] * F[(mm + 3) * ND + tid];
                    }
                    g_Q[irow * ND + tid] = C[irow * ND + tid] + (b0 + b1) + (b2 + b3);
                }
            }
            __syncthreads();
        }
        gbar();

        // ===== phase 2: CTA0 inverts Q_uu (64x64 SPD, register Gauss-Jordan) =====
        if (b == 0) {
            const int r = tid >> 2, q4 = tid & 3;   // row, column quarter (16 cols)
            float ar[16], vi[16];
            #pragma unroll
            for (int jj = 0; jj < 16; ++jj) {
                int col = q4 * 16 + jj;
                ar[jj] = __ldcg(&g_Q[(NX + r) * ND + NX + col]);
                vi[jj] = (col == r) ? 1.0f : 0.0f;
            }
            #pragma unroll
            for (int pv = 0; pv < 64; ++pv) {
                const int ps = pv >> 4, pj = pv & 15;
                if (r == pv && q4 == ps) pivsh = 1.0f / ar[pj];
                __syncthreads();
                const float pvv = pivsh;
                if (r == pv) {
                    #pragma unroll
                    for (int jj = 0; jj < 16; ++jj) {
                        ar[jj] *= pvv; vi[jj] *= pvv;
                        prA[q4 * 16 + jj] = ar[jj];
                        prI[q4 * 16 + jj] = vi[jj];
                    }
                }
                if (q4 == ps) fsh[r] = ar[pj];
                __syncthreads();
                if (r != pv) {
                    const float fr = fsh[r];
                    #pragma unroll
                    for (int jj = 0; jj < 16; ++jj) {
                        ar[jj] -= fr * prA[q4 * 16 + jj];
                        vi[jj] -= fr * prI[q4 * 16 + jj];
                    }
                }
                __syncthreads();
            }
            #pragma unroll
            for (int jj = 0; jj < 16; ++jj) g_inv[r * 64 + q4 * 16 + jj] = vi[jj];
        }
        gbar();

        // ===== phase 3: K = -inv @ Q_ux, k = -inv @ q_u =====
        {
            const int g = b * NT + tid;          // 0..8191 = 64x128
            const int u = g >> 7, xc = g & 127;
            float a0 = 0.f, a1 = 0.f, a2 = 0.f, a3 = 0.f;
            #pragma unroll 4
            for (int mm = 0; mm < NU; mm += 4) {
                a0 += __ldcg(&g_inv[u * NU + mm    ]) * __ldcg(&g_Q[(NX + mm    ) * ND + xc]);
                a1 += __ldcg(&g_inv[u * NU + mm + 1]) * __ldcg(&g_Q[(NX + mm + 1) * ND + xc]);
                a2 += __ldcg(&g_inv[u * NU + mm + 2]) * __ldcg(&g_Q[(NX + mm + 2) * ND + xc]);
                a3 += __ldcg(&g_inv[u * NU + mm + 3]) * __ldcg(&g_Q[(NX + mm + 3) * ND + xc]);
            }
            g_Ks[(size_t)it * (NU * NX) + g] = -((a0 + a1) + (a2 + a3));
            if (g < NU) {
                float s = 0.f;
                #pragma unroll 4
                for (int mm = 0; mm < NU; ++mm)
                    s += __ldcg(&g_inv[g * NU + mm]) * __ldcg(&g_q[NX + mm]);
                g_ks[it * NU + g] = -s;
            }
        }
        gbar();

        // ===== phase 4: V' = Q_xx + Q_xu K, v' = q_x + Q_xu k, M, b, delta =====
        {
            const float* Kit = g_Ks + (size_t)it * (NU * NX);
            float dmax = 0.f, vmx = 0.f;
            const int g = b * NT + tid;
            #pragma unroll
            for (int h = 0; h < 2; ++h) {
                const int e = g + h * (GB * NT);     // 0..16383 = 128x128
                const int i = e >> 7, j = e & 127;
                float a0 = 0.f, a1 = 0.f, m0 = 0.f, m1 = 0.f;
                #pragma unroll 4
                for (int u = 0; u < NU; u += 2) {
                    float k0 = __ldcg(&Kit[(u    ) * NX + j]);
                    float k1 = __ldcg(&Kit[(u + 1) * NX + j]);
                    a0 += __ldcg(&g_Q[i * ND + NX + u    ]) * k0;
                    a1 += __ldcg(&g_Q[i * ND + NX + u + 1]) * k1;
                    m0 += F[i * ND + NX + u    ] * k0;
                    m1 += F[i * ND + NX + u + 1] * k1;
                }
                float vnew = __ldcg(&g_Q[i * ND + j]) + (a0 + a1);
                Vn[e] = vnew;
                dmax = fmaxf(dmax, fabsf(vnew - __ldcg(&V[e])));
                vmx  = fmaxf(vmx, fabsf(vnew));
                g_Ms[(size_t)it * (NX * NX) + e] = F[i * ND + j] + (m0 + m1);
            }
            if (g < NX) {
                float s = 0.f, sb = 0.f;
                #pragma unroll 4
                for (int u = 0; u < NU; ++u) {
                    float kk = __ldcg(&g_ks[it * NU + u]);
                    s  += __ldcg(&g_Q[g * ND + NX + u]) * kk;
                    sb += F[g * ND + NX + u] * kk;
                }
                vn[g] = __ldcg(&g_q[g]) + s;
                g_bs[it * NX + g] = f[g] + sb;
            }
            // CTA reduce max
            #pragma unroll
            for (int o = 16; o > 0; o >>= 1) {
                dmax = fmaxf(dmax, __shfl_down_sync(0xffffffffu, dmax, o));
                vmx  = fmaxf(vmx,  __shfl_down_sync(0xffffffffu, vmx, o));
            }
            if ((tid & 31) == 0) { rmax[tid >> 5] = dmax; rvmx[tid >> 5] = vmx; }
            __syncthreads();
            if (tid == 0) {
                float d = rmax[0], vv = rvmx[0];
                #pragma unroll
                for (int w = 1; w < 8; ++w) { d = fmaxf(d, rmax[w]); vv = fmaxf(vv, rvmx[w]); }
                atomicMax(&g_delta[it], __float_as_uint(d));
                atomicMax(&g_vmax[it], __float_as_uint(vv));
            }
        }
        gbar();

        // ===== convergence check (uniform across grid) =====
        {
            float dd = __uint_as_float(__ldcg(&g_delta[it]));
            float vv = __uint_as_float(__ldcg(&g_vmax[it]));
            if (dd <= 1e-6f * vv) {
                if (b == 0 && tid == 0) g_niters = it + 1;
                break;
            }
        }
    }
}

// ---------------- sequential rollout: x' = M_r x + b_r (one CTA) ----------------
__global__ void __launch_bounds__(256) k_rollout(const float* __restrict__ x0,
                                                 float* __restrict__ out_states) {
    const int tid = threadIdx.x;
    const int row = tid & 127, half = tid >> 7;
    const int ni = g_niters;
    __shared__ float xs[NX];
    __shared__ float ps[256];

    float mreg[64];
    {
        const float* Mc = g_Ms + (size_t)(ni - 1) * (NX * NX) + row * NX + half * 64;
        #pragma unroll
        for (int j = 0; j < 64; j += 4) {
            float4 t4 = *(const float4*)(Mc + j);
            mreg[j] = t4.x; mreg[j + 1] = t4.y; mreg[j + 2] = t4.z; mreg[j + 3] = t4.w;
        }
    }
    float breg = g_bs[(ni - 1) * NX + row];

    if (tid < NX) { xs[tid] = x0[tid]; out_states[tid] = x0[tid]; }
    __syncthreads();

    const int tconv = TH - ni;     // t <= tconv uses converged gains
    for (int t = 0; t < TH; ++t) {
        if (t > tconv) {
            const int r = TH - 1 - t;
            const float* Mr = g_Ms + (size_t)r * (NX * NX) + row * NX + half * 64;
            #pragma unroll
            for (int j = 0; j < 64; j += 4) {
                float4 t4 = *(const float4*)(Mr + j);
                mreg[j] = t4.x; mreg[j + 1] = t4.y; mreg[j + 2] = t4.z; mreg[j + 3] = t4.w;
            }
            breg = g_bs[r * NX + row];
        }
        float a0 = 0.f, a1 = 0.f, a2 = 0.f, a3 = 0.f;
        #pragma unroll
        for (int j = 0; j < 64; j += 4) {
            a0 += mreg[j    ] * xs[half * 64 + j    ];
            a1 += mreg[j + 1] * xs[half * 64 + j + 1];
            a2 += mreg[j + 2] * xs[half * 64 + j + 2];
            a3 += mreg[j + 3] * xs[half * 64 + j + 3];
        }
        ps[tid] = (a0 + a1) + (a2 + a3);
        __syncthreads();
        if (half == 0) {
            float xn = ps[row] + ps[128 + row] + breg;
            xs[row] = xn;
            out_states[(size_t)(t + 1) * NX + row] = xn;
        }
        __syncthreads();
    }
}

// ---------------- parallel epilogue: us + costs ----------------
__global__ void __launch_bounds__(192) k_epilogue(const float* __restrict__ C,
                                                  const float* __restrict__ c,
                                                  const float* __restrict__ states,
                                                  float* __restrict__ us,
                                                  float* __restrict__ costs) {
    const int t = blockIdx.x, tid = threadIdx.x;
    const int ni = g_niters;
    __shared__ float zs[ND];
    __shared__ float red[192];

    if (tid < NX) zs[tid] = states[(size_t)t * NX + tid];
    else zs[tid] = 0.0f;
    __syncthreads();

    if (t < TH && tid < NU) {
        int r = TH - 1 - t; if (r > ni - 1) r = ni - 1;
        const float* Kr = g_Ks + (size_t)r * (NU * NX) + tid * NX;
        float a0 = 0.f, a1 = 0.f, a2 = 0.f, a3 = 0.f;
        #pragma unroll 8
        for (int j = 0; j < NX; j += 4) {
            a0 += Kr[j    ] * zs[j    ];
            a1 += Kr[j + 1] * zs[j + 1];
            a2 += Kr[j + 2] * zs[j + 2];
            a3 += Kr[j + 3] * zs[j + 3];
        }
        float u = g_ks[r * NU + tid] + (a0 + a1) + (a2 + a3);
        zs[NX + tid] = u;
        us[(size_t)t * NU + tid] = u;
    }
    __syncthreads();

    // cost = sum_j z_j * (0.5*(z^T C)_j + c_j)
    float a0 = 0.f, a1 = 0.f, a2 = 0.f, a3 = 0.f;
    #pragma unroll 8
    for (int i = 0; i < ND; i += 4) {
        a0 += zs[i    ] * C[(i    ) * ND + tid];
        a1 += zs[i + 1] * C[(i + 1) * ND + tid];
        a2 += zs[i + 2] * C[(i + 2) * ND + tid];
        a3 += zs[i + 3] * C[(i + 3) * ND + tid];
    }
    float cz = (a0 + a1) + (a2 + a3);
    red[tid] = zs[tid] * (0.5f * cz + c[tid]);
    __syncthreads();
    #pragma unroll
    for (int s = 96; s >= 6; s >>= 1) {
        if (tid < s) red[tid] += red[tid + s];
        __syncthreads();
    }
    if (tid == 0)
        costs[t] = red[0] + red[1] + red[2] + red[3] + red[4] + red[5];
}

// ---------------- launch ----------------
extern "C" void kernel_launch(void* const* d_in, const int* in_sizes, int n_in,
                              void* d_out, int out_size) {
    const float* F  = (const float*)d_in[0];
    const float* f  = (const float*)d_in[1];
    const float* C  = (const float*)d_in[2];
    const float* c  = (const float*)d_in[3];
    const float* x0 = (const float*)d_in[4];
    (void)in_sizes; (void)n_in; (void)out_size;

    float* out        = (float*)d_out;
    float* out_states = out;                                   // (TH+1)*NX
    float* out_us     = out + (size_t)(TH + 1) * NX;           // TH*NU
    float* out_costs  = out_us + (size_t)TH * NU;              // TH+1

    k_setup<<<96, NT>>>(F, C, c);
    k_backward<<<GB, NT>>>(F, f, C, c);
    k_rollout<<<1, 256>>>(x0, out_states);
    k_epilogue<<<TH + 1, 192>>>(C, c, out_states, out_us, out_costs);
}